// round 4
// baseline (speedup 1.0000x reference)
#include <cuda_runtime.h>
#include <math.h>

// Problem constants: B=4, T=2048, D=1024, H=16, HD=64, E=16 -> 64 active tokens
#define SP 65   // padded smem row stride for 16x64 tiles (bank-conflict free)

// ---------------- scratch (device globals: no allocation allowed) ----------------
__device__ float g_xn[64 * 1024];     // LN(x) for 64 active tokens
__device__ float g_q[64 * 1024];      // (b,h,t,d) -> (b*16+h)*1024 + t*64 + d
__device__ float g_k[64 * 1024];
__device__ float g_v[64 * 1024];
__device__ float g_qc2[64 * 1024];    // qcur after iter1 update
__device__ float g_k2[64 * 1024];     // kcur after iter1 (= kl_1)
__device__ float g_v2[64 * 1024];
__device__ float g_ai1[64 * 1024];    // iter_out_1 (active part)
__device__ float g_aflat[64 * 1024];  // attn_out token-major: (b*16+t)*1024 + h*64 + d
__device__ float g_diffpart[64];      // per-(b,h) partial sums of |ai1-ai0|

// ---------------- K_fill: out rows t>=16 are just bo ----------------
__global__ void __launch_bounds__(256) fill_kernel(const float* __restrict__ bo,
                                                   float4* __restrict__ out) {
    int idx = blockIdx.x * 256 + threadIdx.x;      // < 2,097,152 float4
    int row = idx >> 8;                            // 256 float4 per 1024-float row
    int t = row & 2047;
    if (t >= 16) {
        const float4* bo4 = (const float4*)bo;
        out[idx] = __ldg(&bo4[idx & 255]);
    }
}

// ---------------- K_ln: LayerNorm over D=1024 for 64 active tokens ----------------
__global__ void __launch_bounds__(256) ln_kernel(const float* __restrict__ x,
                                                 const float* __restrict__ lna) {
    const int bt = blockIdx.x;            // b*16+t
    const int b = bt >> 4, t = bt & 15;
    const float* xr = x + (size_t)(b * 2048 + t) * 1024;
    __shared__ float xs[1024];
    __shared__ float red[256];
    const int tid = threadIdx.x;

    float s = 0.f;
    for (int i = tid; i < 1024; i += 256) { float v = xr[i]; xs[i] = v; s += v; }
    red[tid] = s; __syncthreads();
    for (int o = 128; o > 0; o >>= 1) { if (tid < o) red[tid] += red[tid + o]; __syncthreads(); }
    float m = red[0] * (1.0f / 1024.0f);
    __syncthreads();

    float s2 = 0.f;
    for (int i = tid; i < 1024; i += 256) { float d = xs[i] - m; s2 = fmaf(d, d, s2); }
    red[tid] = s2; __syncthreads();
    for (int o = 128; o > 0; o >>= 1) { if (tid < o) red[tid] += red[tid + o]; __syncthreads(); }
    float inv = rsqrtf(red[0] * (1.0f / 1024.0f) + 1e-5f);

    for (int i = tid; i < 1024; i += 256)
        g_xn[bt * 1024 + i] = (xs[i] - m) * inv * __ldg(&lna[i]);
}

// ---------------- K_qkv: tiled GEMM, 64 tokens x 64-out tiles, 3 projections ----------------
__global__ void __launch_bounds__(256) qkv_kernel(const float* __restrict__ Wq,
                                                  const float* __restrict__ bq,
                                                  const float* __restrict__ Wk,
                                                  const float* __restrict__ Wv,
                                                  const float* __restrict__ bv) {
    const int o0 = blockIdx.x * 64;
    const int proj = blockIdx.y;                // 0=q, 1=k, 2=v
    const float* W = (proj == 0) ? Wq : ((proj == 1) ? Wk : Wv);
    __shared__ float As[64][SP];
    __shared__ float Ws[64][SP];
    const int tid = threadIdx.x;
    const int tx = tid & 15, ty = tid >> 4;
    float acc[4][4];
#pragma unroll
    for (int i = 0; i < 4; i++)
#pragma unroll
        for (int j = 0; j < 4; j++) acc[i][j] = 0.f;

    for (int k0 = 0; k0 < 1024; k0 += 64) {
#pragma unroll
        for (int l = tid; l < 4096; l += 256) {
            int r = l >> 6, c = l & 63;
            As[r][c] = g_xn[r * 1024 + k0 + c];
            Ws[r][c] = W[(size_t)(o0 + r) * 1024 + k0 + c];
        }
        __syncthreads();
#pragma unroll 8
        for (int kk = 0; kk < 64; kk++) {
            float a[4], w[4];
#pragma unroll
            for (int i = 0; i < 4; i++) a[i] = As[ty * 4 + i][kk];
#pragma unroll
            for (int j = 0; j < 4; j++) w[j] = Ws[tx * 4 + j][kk];
#pragma unroll
            for (int i = 0; i < 4; i++)
#pragma unroll
                for (int j = 0; j < 4; j++) acc[i][j] = fmaf(a[i], w[j], acc[i][j]);
        }
        __syncthreads();
    }

    float* dst = (proj == 0) ? g_q : ((proj == 1) ? g_k : g_v);
    const float SC = 0.35355339059327373f;   // 64^-0.25
#pragma unroll
    for (int i = 0; i < 4; i++) {
        int tk = ty * 4 + i;
        int b = tk >> 4, t = tk & 15;
#pragma unroll
        for (int j = 0; j < 4; j++) {
            int o = o0 + tx * 4 + j;
            float v = acc[i][j];
            if (proj == 0)      v = (v + __ldg(&bq[o])) * SC;
            else if (proj == 1) v = v * SC;
            else                v = v + __ldg(&bv[o]);
            int h = o >> 6, d = o & 63;
            dst[((b * 16 + h) * 16 + t) * 64 + d] = v;
        }
    }
}

// ---------------- per-(b,h) 16x64 micro-matmul: out = in @ W^T + bias ----------------
__device__ __forceinline__ void mm64(int d, int trow,
                                     const float* __restrict__ W,
                                     const float* __restrict__ bias,
                                     const float* in, float* outb) {
    float acc[8];
#pragma unroll
    for (int r = 0; r < 8; r++) acc[r] = 0.f;
#pragma unroll 8
    for (int j = 0; j < 64; j++) {
        float wj = __ldg(&W[d * 64 + j]);
#pragma unroll
        for (int r = 0; r < 8; r++) acc[r] = fmaf(in[(trow + 2 * r) * SP + j], wj, acc[r]);
    }
    float bb = __ldg(&bias[d]);
#pragma unroll
    for (int r = 0; r < 8; r++) outb[(trow + 2 * r) * SP + d] = acc[r] + bb;
}

// One inner-attention iteration for one (b,h): 128 threads.
// Inputs qin/kin/vin (smem, stride SP). Outputs: klo=kl, vlo=vl, aout=ai.
__device__ __forceinline__ void small_iter(int tid,
        const float* __restrict__ Wlq, const float* __restrict__ blq,
        const float* __restrict__ Wlk, const float* __restrict__ blk,
        const float* __restrict__ Wlv, const float* __restrict__ blv,
        const float* __restrict__ lnc, const float* __restrict__ lnd,
        float tscale,
        const float* qin, const float* kin, const float* vin,
        float* tq, float* klo, float* vlo, float* ksb, float* probs, float* aout) {
    const int d = tid & 63;
    const int trow = tid >> 6;   // 0..1
    mm64(d, trow, Wlq, blq, qin, tq);   // ql
    mm64(d, trow, Wlk, blk, kin, klo);  // kl
    mm64(d, trow, Wlv, blv, vin, vlo);  // vl
    __syncthreads();

    // LayerNorm(hd=64) rows: warp0 lanes 0-15 -> qs (in place, *lnc*tscale);
    // warp2 lanes 0-15 -> ks into ksb (klo preserved for next iteration)
    if (tid < 16) {
        int row = tid;
        float m = 0.f;
#pragma unroll 8
        for (int j = 0; j < 64; j++) m += tq[row * SP + j];
        m *= (1.0f / 64.0f);
        float var = 0.f;
#pragma unroll 8
        for (int j = 0; j < 64; j++) { float dd = tq[row * SP + j] - m; var = fmaf(dd, dd, var); }
        float inv = rsqrtf(var * (1.0f / 64.0f) + 1e-5f);
#pragma unroll 8
        for (int j = 0; j < 64; j++)
            tq[row * SP + j] = (tq[row * SP + j] - m) * inv * __ldg(&lnc[j]) * tscale;
    } else if (tid >= 64 && tid < 80) {
        int row = tid - 64;
        float m = 0.f;
#pragma unroll 8
        for (int j = 0; j < 64; j++) m += klo[row * SP + j];
        m *= (1.0f / 64.0f);
        float var = 0.f;
#pragma unroll 8
        for (int j = 0; j < 64; j++) { float dd = klo[row * SP + j] - m; var = fmaf(dd, dd, var); }
        float inv = rsqrtf(var * (1.0f / 64.0f) + 1e-5f);
#pragma unroll 8
        for (int j = 0; j < 64; j++)
            ksb[row * SP + j] = (klo[row * SP + j] - m) * inv * __ldg(&lnd[j]);
    }
    __syncthreads();

    // logits (16x16) * 1/sqrt(64)
#pragma unroll
    for (int e0 = 0; e0 < 2; e0++) {
        int e = tid + e0 * 128;
        int t = e >> 4, s = e & 15;
        float acc = 0.f;
#pragma unroll 8
        for (int j = 0; j < 64; j++) acc = fmaf(tq[t * SP + j], ksb[s * SP + j], acc);
        probs[e] = acc * 0.125f;
    }
    __syncthreads();

    // softmax rows
    if (tid < 16) {
        float mx = -3.402823466e38f;
#pragma unroll
        for (int s = 0; s < 16; s++) mx = fmaxf(mx, probs[tid * 16 + s]);
        float sm = 0.f;
#pragma unroll
        for (int s = 0; s < 16; s++) {
            float ex = expf(probs[tid * 16 + s] - mx);
            probs[tid * 16 + s] = ex; sm += ex;
        }
        float rinv = 1.0f / sm;
#pragma unroll
        for (int s = 0; s < 16; s++) probs[tid * 16 + s] *= rinv;
    }
    __syncthreads();

    // ai = probs @ vl
    {
        float acc[8];
#pragma unroll
        for (int r = 0; r < 8; r++) acc[r] = 0.f;
#pragma unroll
        for (int s = 0; s < 16; s++) {
            float vv = vlo[s * SP + d];
#pragma unroll
            for (int r = 0; r < 8; r++) acc[r] = fmaf(probs[(trow + 2 * r) * 16 + s], vv, acc[r]);
        }
#pragma unroll
        for (int r = 0; r < 8; r++) aout[(trow + 2 * r) * SP + d] = acc[r];
    }
    __syncthreads();
}

// ---------------- K_iter01: iterations 0 and 1, diff partial sums ----------------
__global__ void __launch_bounds__(128) iter01_kernel(
        const float* __restrict__ Wlq, const float* __restrict__ blq,
        const float* __restrict__ Wlk, const float* __restrict__ blk,
        const float* __restrict__ Wlv, const float* __restrict__ blv,
        const float* __restrict__ lnc, const float* __restrict__ lnd,
        const float* __restrict__ temp) {
    __shared__ float qin[16 * SP], kin[16 * SP], vin[16 * SP];
    __shared__ float tq[16 * SP], klA[16 * SP], vlA[16 * SP], ksb[16 * SP];
    __shared__ float ai0[16 * SP], ai1[16 * SP];
    __shared__ float probs[256];
    __shared__ float red[128];
    const int bx = blockIdx.x, tid = threadIdx.x;
    const int base = bx * 1024;

    for (int e = tid; e < 1024; e += 128) {
        int t = e >> 6, dd = e & 63, idx = t * SP + dd;
        qin[idx] = g_q[base + e]; kin[idx] = g_k[base + e]; vin[idx] = g_v[base + e];
    }
    __syncthreads();

    const float temp0 = __ldg(temp);
    float t0 = temp0;
    float ts0 = (t0 != 1.0f && t0 > 0.0f) ? rsqrtf(t0) : 1.0f;
    small_iter(tid, Wlq, blq, Wlk, blk, Wlv, blv, lnc, lnd, ts0,
               qin, kin, vin, tq, klA, vlA, ksb, probs, ai0);

    // qcur += iter_out_0
    for (int e = tid; e < 1024; e += 128) {
        int t = e >> 6, dd = e & 63;
        qin[t * SP + dd] += ai0[t * SP + dd];
    }
    __syncthreads();

    float t1 = temp0 + 0.005f;
    float ts1 = (t1 != 1.0f && t1 > 0.0f) ? rsqrtf(t1) : 1.0f;
    // kin/vin buffers are free now: reuse as kl1/vl1 outputs
    small_iter(tid, Wlq, blq, Wlk, blk, Wlv, blv, lnc, lnd, ts1,
               qin, klA, vlA, tq, kin, vin, ksb, probs, ai1);

    float psum = 0.f;
    for (int e = tid; e < 1024; e += 128) {
        int t = e >> 6, dd = e & 63, idx = t * SP + dd;
        float a1 = ai1[idx];
        psum += fabsf(a1 - ai0[idx]);
        g_ai1[base + e] = a1;
        g_qc2[base + e] = qin[idx] + a1;   // q + ai0 + ai1
        g_k2[base + e] = kin[idx];          // kl_1
        g_v2[base + e] = vin[idx];          // vl_1
    }
    red[tid] = psum; __syncthreads();
#pragma unroll
    for (int o = 64; o > 0; o >>= 1) { if (tid < o) red[tid] += red[tid + o]; __syncthreads(); }
    if (tid == 0) g_diffpart[bx] = red[0];
}

// ---------------- K_iter2: deterministic diff, conditional iteration 2 ----------------
__global__ void __launch_bounds__(128) iter2_kernel(
        const float* __restrict__ Wlq, const float* __restrict__ blq,
        const float* __restrict__ Wlk, const float* __restrict__ blk,
        const float* __restrict__ Wlv, const float* __restrict__ blv,
        const float* __restrict__ lnc, const float* __restrict__ lnd,
        const float* __restrict__ temp, const float* __restrict__ thrp,
        const float* __restrict__ facp) {
    __shared__ float qin[16 * SP], kin[16 * SP], vin[16 * SP];
    __shared__ float tq[16 * SP], klA[16 * SP], vlA[16 * SP], ksb[16 * SP];
    __shared__ float ai2[16 * SP];
    __shared__ float probs[256];
    __shared__ float sdiff;
    const int bx = blockIdx.x, tid = threadIdx.x;
    const int b = bx >> 4, h = bx & 15;

    if (tid == 0) {
        float s = 0.f;
        for (int i = 0; i < 64; i++) s += g_diffpart[i];   // fixed order: deterministic
        sdiff = s * (1.0f / 8388608.0f);                   // mean over B*H*T*hd
    }
    __syncthreads();
    float diff = sdiff;
    float thr = __ldg(thrp), fac = __ldg(facp);
    bool done = diff < (thr + fac * diff);

    if (done) {
        for (int e = tid; e < 1024; e += 128) {
            int t = e >> 6, dd = e & 63;
            g_aflat[(b * 16 + t) * 1024 + h * 64 + dd] = g_ai1[bx * 1024 + e];
        }
        return;
    }

    for (int e = tid; e < 1024; e += 128) {
        int t = e >> 6, dd = e & 63, idx = t * SP + dd;
        qin[idx] = g_qc2[bx * 1024 + e];
        kin[idx] = g_k2[bx * 1024 + e];
        vin[idx] = g_v2[bx * 1024 + e];
    }
    __syncthreads();

    float t2 = __ldg(temp) + 0.01f;
    float ts2 = (t2 != 1.0f && t2 > 0.0f) ? rsqrtf(t2) : 1.0f;
    small_iter(tid, Wlq, blq, Wlk, blk, Wlv, blv, lnc, lnd, ts2,
               qin, kin, vin, tq, klA, vlA, ksb, probs, ai2);

    for (int e = tid; e < 1024; e += 128) {
        int t = e >> 6, dd = e & 63;
        g_aflat[(b * 16 + t) * 1024 + h * 64 + dd] = ai2[t * SP + dd];
    }
}

// ---------------- K_outproj: out rows t<16 = attn_flat @ Wo^T + bo ----------------
__global__ void __launch_bounds__(256) outproj_kernel(const float* __restrict__ Wo,
                                                      const float* __restrict__ bo,
                                                      float* __restrict__ out) {
    const int o0 = blockIdx.x * 64;
    __shared__ float As[64][SP];
    __shared__ float Ws[64][SP];
    const int tid = threadIdx.x;
    const int tx = tid & 15, ty = tid >> 4;
    float acc[4][4];
#pragma unroll
    for (int i = 0; i < 4; i++)
#pragma unroll
        for (int j = 0; j < 4; j++) acc[i][j] = 0.f;

    for (int k0 = 0; k0 < 1024; k0 += 64) {
#pragma unroll
        for (int l = tid; l < 4096; l += 256) {
            int r = l >> 6, c = l & 63;
            As[r][c] = g_aflat[r * 1024 + k0 + c];
            Ws[r][c] = Wo[(size_t)(o0 + r) * 1024 + k0 + c];
        }
        __syncthreads();
#pragma unroll 8
        for (int kk = 0; kk < 64; kk++) {
            float a[4], w[4];
#pragma unroll
            for (int i = 0; i < 4; i++) a[i] = As[ty * 4 + i][kk];
#pragma unroll
            for (int j = 0; j < 4; j++) w[j] = Ws[tx * 4 + j][kk];
#pragma unroll
            for (int i = 0; i < 4; i++)
#pragma unroll
                for (int j = 0; j < 4; j++) acc[i][j] = fmaf(a[i], w[j], acc[i][j]);
        }
        __syncthreads();
    }
#pragma unroll
    for (int i = 0; i < 4; i++) {
        int tk = ty * 4 + i;
        int b = tk >> 4, t = tk & 15;
#pragma unroll
        for (int j = 0; j < 4; j++) {
            int o = o0 + tx * 4 + j;
            out[(size_t)(b * 2048 + t) * 1024 + o] = acc[i][j] + __ldg(&bo[o]);
        }
    }
}

extern "C" void kernel_launch(void* const* d_in, const int* in_sizes, int n_in,
                              void* d_out, int out_size) {
    const float* x    = (const float*)d_in[0];
    const float* Wq   = (const float*)d_in[1];
    const float* bq   = (const float*)d_in[2];
    const float* Wk   = (const float*)d_in[3];
    const float* Wv   = (const float*)d_in[4];
    const float* bv   = (const float*)d_in[5];
    const float* Wo   = (const float*)d_in[6];
    const float* bo   = (const float*)d_in[7];
    const float* lna  = (const float*)d_in[8];
    const float* lnc  = (const float*)d_in[9];
    const float* lnd  = (const float*)d_in[10];
    const float* Wlq  = (const float*)d_in[11];
    const float* blq  = (const float*)d_in[12];
    const float* Wlk  = (const float*)d_in[13];
    const float* blk  = (const float*)d_in[14];
    const float* Wlv  = (const float*)d_in[15];
    const float* blv  = (const float*)d_in[16];
    const float* temp = (const float*)d_in[17];
    const float* thr  = (const float*)d_in[18];
    const float* fac  = (const float*)d_in[19];
    float* out = (float*)d_out;

    fill_kernel<<<8192, 256>>>(bo, (float4*)out);                 // t>=16 rows = bo
    ln_kernel<<<64, 256>>>(x, lna);                               // LN for 64 active tokens
    qkv_kernel<<<dim3(16, 3), 256>>>(Wq, bq, Wk, Wv, bv);         // q/k/v projections
    iter01_kernel<<<64, 128>>>(Wlq, blq, Wlk, blk, Wlv, blv, lnc, lnd, temp);
    iter2_kernel<<<64, 128>>>(Wlq, blq, Wlk, blk, Wlv, blv, lnc, lnd, temp, thr, fac);
    outproj_kernel<<<16, 256>>>(Wo, bo, out);                     // t<16 rows
}

// round 5
// speedup vs baseline: 1.0021x; 1.0021x over previous
#include <cuda_runtime.h>
#include <math.h>

// Problem constants: B=4, T=2048, D=1024, H=16, HD=64, E=16 -> 64 active tokens
#define SP 65   // padded smem row stride for 16x64 tiles (bank-conflict free)

// ---------------- scratch (device globals: no allocation allowed) ----------------
__device__ float g_xn[64 * 1024];     // LN(x) for 64 active tokens
__device__ float g_q[64 * 1024];      // (b,h,t,d) -> (b*16+h)*1024 + t*64 + d
__device__ float g_k[64 * 1024];
__device__ float g_v[64 * 1024];
__device__ float g_qc2[64 * 1024];    // qcur after iter1 update
__device__ float g_k2[64 * 1024];     // kcur after iter1 (= kl_1)
__device__ float g_v2[64 * 1024];
__device__ float g_ai1[64 * 1024];    // iter_out_1 (active part)
__device__ float g_aflat[64 * 1024];  // attn_out token-major: (b*16+t)*1024 + h*64 + d
__device__ float g_diffpart[64];      // per-(b,h) partial sums of |ai1-ai0|

// ---------------- K_fill: out rows t>=16 are just bo ----------------
__global__ void __launch_bounds__(256) fill_kernel(const float* __restrict__ bo,
                                                   float4* __restrict__ out) {
    int idx = blockIdx.x * 256 + threadIdx.x;      // < 2,097,152 float4
    int row = idx >> 8;                            // 256 float4 per 1024-float row
    int t = row & 2047;
    if (t >= 16) {
        const float4* bo4 = (const float4*)bo;
        out[idx] = __ldg(&bo4[idx & 255]);
    }
}

// ---------------- K_ln: LayerNorm over D=1024 for 64 active tokens ----------------
__global__ void __launch_bounds__(256) ln_kernel(const float* __restrict__ x,
                                                 const float* __restrict__ lna) {
    const int bt = blockIdx.x;            // b*16+t
    const int b = bt >> 4, t = bt & 15;
    const float* xr = x + (size_t)(b * 2048 + t) * 1024;
    __shared__ float xs[1024];
    __shared__ float red[256];
    const int tid = threadIdx.x;

    float s = 0.f;
    for (int i = tid; i < 1024; i += 256) { float v = xr[i]; xs[i] = v; s += v; }
    red[tid] = s; __syncthreads();
    for (int o = 128; o > 0; o >>= 1) { if (tid < o) red[tid] += red[tid + o]; __syncthreads(); }
    float m = red[0] * (1.0f / 1024.0f);
    __syncthreads();

    float s2 = 0.f;
    for (int i = tid; i < 1024; i += 256) { float d = xs[i] - m; s2 = fmaf(d, d, s2); }
    red[tid] = s2; __syncthreads();
    for (int o = 128; o > 0; o >>= 1) { if (tid < o) red[tid] += red[tid + o]; __syncthreads(); }
    float inv = rsqrtf(red[0] * (1.0f / 1024.0f) + 1e-5f);

    for (int i = tid; i < 1024; i += 256)
        g_xn[bt * 1024 + i] = (xs[i] - m) * inv * __ldg(&lna[i]);
}

// ---------------- K_qkv: tiled GEMM, 64 tokens x 64-out tiles, 3 projections ----------------
__global__ void __launch_bounds__(256) qkv_kernel(const float* __restrict__ Wq,
                                                  const float* __restrict__ bq,
                                                  const float* __restrict__ Wk,
                                                  const float* __restrict__ Wv,
                                                  const float* __restrict__ bv) {
    const int o0 = blockIdx.x * 64;
    const int proj = blockIdx.y;                // 0=q, 1=k, 2=v
    const float* W = (proj == 0) ? Wq : ((proj == 1) ? Wk : Wv);
    __shared__ float As[64][SP];
    __shared__ float Ws[64][SP];
    const int tid = threadIdx.x;
    const int tx = tid & 15, ty = tid >> 4;
    float acc[4][4];
#pragma unroll
    for (int i = 0; i < 4; i++)
#pragma unroll
        for (int j = 0; j < 4; j++) acc[i][j] = 0.f;

    for (int k0 = 0; k0 < 1024; k0 += 64) {
#pragma unroll
        for (int l = tid; l < 4096; l += 256) {
            int r = l >> 6, c = l & 63;
            As[r][c] = g_xn[r * 1024 + k0 + c];
            Ws[r][c] = W[(size_t)(o0 + r) * 1024 + k0 + c];
        }
        __syncthreads();
#pragma unroll 8
        for (int kk = 0; kk < 64; kk++) {
            float a[4], w[4];
#pragma unroll
            for (int i = 0; i < 4; i++) a[i] = As[ty * 4 + i][kk];
#pragma unroll
            for (int j = 0; j < 4; j++) w[j] = Ws[tx * 4 + j][kk];
#pragma unroll
            for (int i = 0; i < 4; i++)
#pragma unroll
                for (int j = 0; j < 4; j++) acc[i][j] = fmaf(a[i], w[j], acc[i][j]);
        }
        __syncthreads();
    }

    float* dst = (proj == 0) ? g_q : ((proj == 1) ? g_k : g_v);
    const float SC = 0.35355339059327373f;   // 64^-0.25
#pragma unroll
    for (int i = 0; i < 4; i++) {
        int tk = ty * 4 + i;
        int b = tk >> 4, t = tk & 15;
#pragma unroll
        for (int j = 0; j < 4; j++) {
            int o = o0 + tx * 4 + j;
            float v = acc[i][j];
            if (proj == 0)      v = (v + __ldg(&bq[o])) * SC;
            else if (proj == 1) v = v * SC;
            else                v = v + __ldg(&bv[o]);
            int h = o >> 6, d = o & 63;
            dst[((b * 16 + h) * 16 + t) * 64 + d] = v;
        }
    }
}

// ---------------- per-(b,h) 16x64 micro-matmul: out = in @ W^T + bias ----------------
__device__ __forceinline__ void mm64(int d, int trow,
                                     const float* __restrict__ W,
                                     const float* __restrict__ bias,
                                     const float* in, float* outb) {
    float acc[8];
#pragma unroll
    for (int r = 0; r < 8; r++) acc[r] = 0.f;
#pragma unroll 8
    for (int j = 0; j < 64; j++) {
        float wj = __ldg(&W[d * 64 + j]);
#pragma unroll
        for (int r = 0; r < 8; r++) acc[r] = fmaf(in[(trow + 2 * r) * SP + j], wj, acc[r]);
    }
    float bb = __ldg(&bias[d]);
#pragma unroll
    for (int r = 0; r < 8; r++) outb[(trow + 2 * r) * SP + d] = acc[r] + bb;
}

// One inner-attention iteration for one (b,h): 128 threads.
// Inputs qin/kin/vin (smem, stride SP). Outputs: klo=kl, vlo=vl, aout=ai.
__device__ __forceinline__ void small_iter(int tid,
        const float* __restrict__ Wlq, const float* __restrict__ blq,
        const float* __restrict__ Wlk, const float* __restrict__ blk,
        const float* __restrict__ Wlv, const float* __restrict__ blv,
        const float* __restrict__ lnc, const float* __restrict__ lnd,
        float tscale,
        const float* qin, const float* kin, const float* vin,
        float* tq, float* klo, float* vlo, float* ksb, float* probs, float* aout) {
    const int d = tid & 63;
    const int trow = tid >> 6;   // 0..1
    mm64(d, trow, Wlq, blq, qin, tq);   // ql
    mm64(d, trow, Wlk, blk, kin, klo);  // kl
    mm64(d, trow, Wlv, blv, vin, vlo);  // vl
    __syncthreads();

    // LayerNorm(hd=64) rows: warp0 lanes 0-15 -> qs (in place, *lnc*tscale);
    // warp2 lanes 0-15 -> ks into ksb (klo preserved for next iteration)
    if (tid < 16) {
        int row = tid;
        float m = 0.f;
#pragma unroll 8
        for (int j = 0; j < 64; j++) m += tq[row * SP + j];
        m *= (1.0f / 64.0f);
        float var = 0.f;
#pragma unroll 8
        for (int j = 0; j < 64; j++) { float dd = tq[row * SP + j] - m; var = fmaf(dd, dd, var); }
        float inv = rsqrtf(var * (1.0f / 64.0f) + 1e-5f);
#pragma unroll 8
        for (int j = 0; j < 64; j++)
            tq[row * SP + j] = (tq[row * SP + j] - m) * inv * __ldg(&lnc[j]) * tscale;
    } else if (tid >= 64 && tid < 80) {
        int row = tid - 64;
        float m = 0.f;
#pragma unroll 8
        for (int j = 0; j < 64; j++) m += klo[row * SP + j];
        m *= (1.0f / 64.0f);
        float var = 0.f;
#pragma unroll 8
        for (int j = 0; j < 64; j++) { float dd = klo[row * SP + j] - m; var = fmaf(dd, dd, var); }
        float inv = rsqrtf(var * (1.0f / 64.0f) + 1e-5f);
#pragma unroll 8
        for (int j = 0; j < 64; j++)
            ksb[row * SP + j] = (klo[row * SP + j] - m) * inv * __ldg(&lnd[j]);
    }
    __syncthreads();

    // logits (16x16) * 1/sqrt(64)
#pragma unroll
    for (int e0 = 0; e0 < 2; e0++) {
        int e = tid + e0 * 128;
        int t = e >> 4, s = e & 15;
        float acc = 0.f;
#pragma unroll 8
        for (int j = 0; j < 64; j++) acc = fmaf(tq[t * SP + j], ksb[s * SP + j], acc);
        probs[e] = acc * 0.125f;
    }
    __syncthreads();

    // softmax rows
    if (tid < 16) {
        float mx = -3.402823466e38f;
#pragma unroll
        for (int s = 0; s < 16; s++) mx = fmaxf(mx, probs[tid * 16 + s]);
        float sm = 0.f;
#pragma unroll
        for (int s = 0; s < 16; s++) {
            float ex = expf(probs[tid * 16 + s] - mx);
            probs[tid * 16 + s] = ex; sm += ex;
        }
        float rinv = 1.0f / sm;
#pragma unroll
        for (int s = 0; s < 16; s++) probs[tid * 16 + s] *= rinv;
    }
    __syncthreads();

    // ai = probs @ vl
    {
        float acc[8];
#pragma unroll
        for (int r = 0; r < 8; r++) acc[r] = 0.f;
#pragma unroll
        for (int s = 0; s < 16; s++) {
            float vv = vlo[s * SP + d];
#pragma unroll
            for (int r = 0; r < 8; r++) acc[r] = fmaf(probs[(trow + 2 * r) * 16 + s], vv, acc[r]);
        }
#pragma unroll
        for (int r = 0; r < 8; r++) aout[(trow + 2 * r) * SP + d] = acc[r];
    }
    __syncthreads();
}

// ---------------- K_iter01: iterations 0 and 1, diff partial sums ----------------
__global__ void __launch_bounds__(128) iter01_kernel(
        const float* __restrict__ Wlq, const float* __restrict__ blq,
        const float* __restrict__ Wlk, const float* __restrict__ blk,
        const float* __restrict__ Wlv, const float* __restrict__ blv,
        const float* __restrict__ lnc, const float* __restrict__ lnd,
        const float* __restrict__ temp) {
    __shared__ float qin[16 * SP], kin[16 * SP], vin[16 * SP];
    __shared__ float tq[16 * SP], klA[16 * SP], vlA[16 * SP], ksb[16 * SP];
    __shared__ float ai0[16 * SP], ai1[16 * SP];
    __shared__ float probs[256];
    __shared__ float red[128];
    const int bx = blockIdx.x, tid = threadIdx.x;
    const int base = bx * 1024;

    for (int e = tid; e < 1024; e += 128) {
        int t = e >> 6, dd = e & 63, idx = t * SP + dd;
        qin[idx] = g_q[base + e]; kin[idx] = g_k[base + e]; vin[idx] = g_v[base + e];
    }
    __syncthreads();

    const float temp0 = __ldg(temp);
    float t0 = temp0;
    float ts0 = (t0 != 1.0f && t0 > 0.0f) ? rsqrtf(t0) : 1.0f;
    small_iter(tid, Wlq, blq, Wlk, blk, Wlv, blv, lnc, lnd, ts0,
               qin, kin, vin, tq, klA, vlA, ksb, probs, ai0);

    // qcur += iter_out_0
    for (int e = tid; e < 1024; e += 128) {
        int t = e >> 6, dd = e & 63;
        qin[t * SP + dd] += ai0[t * SP + dd];
    }
    __syncthreads();

    float t1 = temp0 + 0.005f;
    float ts1 = (t1 != 1.0f && t1 > 0.0f) ? rsqrtf(t1) : 1.0f;
    // kin/vin buffers are free now: reuse as kl1/vl1 outputs
    small_iter(tid, Wlq, blq, Wlk, blk, Wlv, blv, lnc, lnd, ts1,
               qin, klA, vlA, tq, kin, vin, ksb, probs, ai1);

    float psum = 0.f;
    for (int e = tid; e < 1024; e += 128) {
        int t = e >> 6, dd = e & 63, idx = t * SP + dd;
        float a1 = ai1[idx];
        psum += fabsf(a1 - ai0[idx]);
        g_ai1[base + e] = a1;
        g_qc2[base + e] = qin[idx] + a1;   // q + ai0 + ai1
        g_k2[base + e] = kin[idx];          // kl_1
        g_v2[base + e] = vin[idx];          // vl_1
    }
    red[tid] = psum; __syncthreads();
#pragma unroll
    for (int o = 64; o > 0; o >>= 1) { if (tid < o) red[tid] += red[tid + o]; __syncthreads(); }
    if (tid == 0) g_diffpart[bx] = red[0];
}

// ---------------- K_iter2: deterministic diff, conditional iteration 2 ----------------
__global__ void __launch_bounds__(128) iter2_kernel(
        const float* __restrict__ Wlq, const float* __restrict__ blq,
        const float* __restrict__ Wlk, const float* __restrict__ blk,
        const float* __restrict__ Wlv, const float* __restrict__ blv,
        const float* __restrict__ lnc, const float* __restrict__ lnd,
        const float* __restrict__ temp, const float* __restrict__ thrp,
        const float* __restrict__ facp) {
    __shared__ float qin[16 * SP], kin[16 * SP], vin[16 * SP];
    __shared__ float tq[16 * SP], klA[16 * SP], vlA[16 * SP], ksb[16 * SP];
    __shared__ float ai2[16 * SP];
    __shared__ float probs[256];
    __shared__ float sdiff;
    const int bx = blockIdx.x, tid = threadIdx.x;
    const int b = bx >> 4, h = bx & 15;

    if (tid == 0) {
        float s = 0.f;
        for (int i = 0; i < 64; i++) s += g_diffpart[i];   // fixed order: deterministic
        sdiff = s * (1.0f / 8388608.0f);                   // mean over B*H*T*hd
    }
    __syncthreads();
    float diff = sdiff;
    float thr = __ldg(thrp), fac = __ldg(facp);
    bool done = diff < (thr + fac * diff);

    if (done) {
        for (int e = tid; e < 1024; e += 128) {
            int t = e >> 6, dd = e & 63;
            g_aflat[(b * 16 + t) * 1024 + h * 64 + dd] = g_ai1[bx * 1024 + e];
        }
        return;
    }

    for (int e = tid; e < 1024; e += 128) {
        int t = e >> 6, dd = e & 63, idx = t * SP + dd;
        qin[idx] = g_qc2[bx * 1024 + e];
        kin[idx] = g_k2[bx * 1024 + e];
        vin[idx] = g_v2[bx * 1024 + e];
    }
    __syncthreads();

    float t2 = __ldg(temp) + 0.01f;
    float ts2 = (t2 != 1.0f && t2 > 0.0f) ? rsqrtf(t2) : 1.0f;
    small_iter(tid, Wlq, blq, Wlk, blk, Wlv, blv, lnc, lnd, ts2,
               qin, kin, vin, tq, klA, vlA, ksb, probs, ai2);

    for (int e = tid; e < 1024; e += 128) {
        int t = e >> 6, dd = e & 63;
        g_aflat[(b * 16 + t) * 1024 + h * 64 + dd] = ai2[t * SP + dd];
    }
}

// ---------------- K_outproj: out rows t<16 = attn_flat @ Wo^T + bo ----------------
__global__ void __launch_bounds__(256) outproj_kernel(const float* __restrict__ Wo,
                                                      const float* __restrict__ bo,
                                                      float* __restrict__ out) {
    const int o0 = blockIdx.x * 64;
    __shared__ float As[64][SP];
    __shared__ float Ws[64][SP];
    const int tid = threadIdx.x;
    const int tx = tid & 15, ty = tid >> 4;
    float acc[4][4];
#pragma unroll
    for (int i = 0; i < 4; i++)
#pragma unroll
        for (int j = 0; j < 4; j++) acc[i][j] = 0.f;

    for (int k0 = 0; k0 < 1024; k0 += 64) {
#pragma unroll
        for (int l = tid; l < 4096; l += 256) {
            int r = l >> 6, c = l & 63;
            As[r][c] = g_aflat[r * 1024 + k0 + c];
            Ws[r][c] = Wo[(size_t)(o0 + r) * 1024 + k0 + c];
        }
        __syncthreads();
#pragma unroll 8
        for (int kk = 0; kk < 64; kk++) {
            float a[4], w[4];
#pragma unroll
            for (int i = 0; i < 4; i++) a[i] = As[ty * 4 + i][kk];
#pragma unroll
            for (int j = 0; j < 4; j++) w[j] = Ws[tx * 4 + j][kk];
#pragma unroll
            for (int i = 0; i < 4; i++)
#pragma unroll
                for (int j = 0; j < 4; j++) acc[i][j] = fmaf(a[i], w[j], acc[i][j]);
        }
        __syncthreads();
    }
#pragma unroll
    for (int i = 0; i < 4; i++) {
        int tk = ty * 4 + i;
        int b = tk >> 4, t = tk & 15;
#pragma unroll
        for (int j = 0; j < 4; j++) {
            int o = o0 + tx * 4 + j;
            out[(size_t)(b * 2048 + t) * 1024 + o] = acc[i][j] + __ldg(&bo[o]);
        }
    }
}

extern "C" void kernel_launch(void* const* d_in, const int* in_sizes, int n_in,
                              void* d_out, int out_size) {
    const float* x    = (const float*)d_in[0];
    const float* Wq   = (const float*)d_in[1];
    const float* bq   = (const float*)d_in[2];
    const float* Wk   = (const float*)d_in[3];
    const float* Wv   = (const float*)d_in[4];
    const float* bv   = (const float*)d_in[5];
    const float* Wo   = (const float*)d_in[6];
    const float* bo   = (const float*)d_in[7];
    const float* lna  = (const float*)d_in[8];
    const float* lnc  = (const float*)d_in[9];
    const float* lnd  = (const float*)d_in[10];
    const float* Wlq  = (const float*)d_in[11];
    const float* blq  = (const float*)d_in[12];
    const float* Wlk  = (const float*)d_in[13];
    const float* blk  = (const float*)d_in[14];
    const float* Wlv  = (const float*)d_in[15];
    const float* blv  = (const float*)d_in[16];
    const float* temp = (const float*)d_in[17];
    const float* thr  = (const float*)d_in[18];
    const float* fac  = (const float*)d_in[19];
    float* out = (float*)d_out;

    fill_kernel<<<8192, 256>>>(bo, (float4*)out);                 // t>=16 rows = bo
    ln_kernel<<<64, 256>>>(x, lna);                               // LN for 64 active tokens
    qkv_kernel<<<dim3(16, 3), 256>>>(Wq, bq, Wk, Wv, bv);         // q/k/v projections
    iter01_kernel<<<64, 128>>>(Wlq, blq, Wlk, blk, Wlv, blv, lnc, lnd, temp);
    iter2_kernel<<<64, 128>>>(Wlq, blq, Wlk, blk, Wlv, blv, lnc, lnd, temp, thr, fac);
    outproj_kernel<<<16, 256>>>(Wo, bo, out);                     // t<16 rows
}

// round 8
// speedup vs baseline: 3.0657x; 3.0592x over previous
#include <cuda_runtime.h>
#include <math.h>

// B=4, T=2048, D=1024, H=16, HD=64, E=16 -> 64 active tokens total
#define SP  68   // iter tile stride (float4-aligned, low-conflict)
#define SPP 65   // GEMM tile stride

// ---------------- scratch ----------------
__device__ float g_xn[64 * 1024];          // LN(x), token-major [tok*1024 + o]
__device__ float g_qkvp[24 * 64 * 1024];   // qkv split-K partials [proj*8+chunk][tok*1024+o]
__device__ float g_outp[8 * 64 * 1024];    // outproj partials [chunk][tok*1024+o]
__device__ float g_qc2[64 * 1024];         // qcur after iter1   [(b*16+h)*1024 + t*64+d]
__device__ float g_k2[64 * 1024];
__device__ float g_v2[64 * 1024];
__device__ float g_ai1[64 * 1024];
__device__ float g_aflat[64 * 1024];       // attn_out token-major [tok*1024 + h*64+d]
__device__ float g_diffpart[64];

// smem layout for iter kernels (floats)
#define WT_SZ   (64 * SP)       // 4352
#define TILE_SZ (16 * SP)       // 1088
#define OFF_WTQ 0
#define OFF_WTK (WT_SZ)
#define OFF_WTV (2 * WT_SZ)
#define OFF_QIN (3 * WT_SZ)
#define OFF_KIN (OFF_QIN + TILE_SZ)
#define OFF_VIN (OFF_KIN + TILE_SZ)
#define OFF_TQ  (OFF_VIN + TILE_SZ)
#define OFF_KLO (OFF_TQ + TILE_SZ)
#define OFF_VLO (OFF_KLO + TILE_SZ)
#define OFF_KSB (OFF_VLO + TILE_SZ)
#define OFF_PRB (OFF_KSB + TILE_SZ)
#define SMEM_ITER_FLOATS (OFF_PRB + 256)
#define SMEM_ITER_BYTES (SMEM_ITER_FLOATS * 4)

// ---------------- K_fill: whole output = bo (t<16 overwritten later) ----------------
__global__ void __launch_bounds__(256) fill_kernel(const float* __restrict__ bo,
                                                   float4* __restrict__ out) {
    int idx = blockIdx.x * 256 + threadIdx.x;      // < 2,097,152 float4
    const float4* bo4 = (const float4*)bo;
    out[idx] = __ldg(&bo4[idx & 255]);
}

// ---------------- K_ln: LayerNorm over D=1024 for 64 active tokens ----------------
__global__ void __launch_bounds__(256) ln_kernel(const float* __restrict__ x,
                                                 const float* __restrict__ lna) {
    const int bt = blockIdx.x;            // tok = b*16+t
    const int b = bt >> 4, t = bt & 15;
    const int tid = threadIdx.x;
    const int wid = tid >> 5, lane = tid & 31;
    const float4* xr = (const float4*)(x + (size_t)(b * 2048 + t) * 1024);
    __shared__ float wp[8];
    __shared__ float stat[2];

    float4 v = __ldg(&xr[tid]);
    float s = (v.x + v.y) + (v.z + v.w);
#pragma unroll
    for (int o = 16; o > 0; o >>= 1) s += __shfl_xor_sync(0xffffffffu, s, o);
    if (lane == 0) wp[wid] = s;
    __syncthreads();
    if (tid == 0) {
        float m = 0.f;
#pragma unroll
        for (int i = 0; i < 8; i++) m += wp[i];
        stat[0] = m * (1.0f / 1024.0f);
    }
    __syncthreads();
    float m = stat[0];
    float dx = v.x - m, dy = v.y - m, dz = v.z - m, dw = v.w - m;
    float q = fmaf(dx, dx, dy * dy) + fmaf(dz, dz, dw * dw);
#pragma unroll
    for (int o = 16; o > 0; o >>= 1) q += __shfl_xor_sync(0xffffffffu, q, o);
    if (lane == 0) wp[wid] = q;
    __syncthreads();
    if (tid == 0) {
        float vv = 0.f;
#pragma unroll
        for (int i = 0; i < 8; i++) vv += wp[i];
        stat[1] = rsqrtf(vv * (1.0f / 1024.0f) + 1e-5f);
    }
    __syncthreads();
    float inv = stat[1];
    float4 w = __ldg(&((const float4*)lna)[tid]);
    float4 r;
    r.x = dx * inv * w.x; r.y = dy * inv * w.y;
    r.z = dz * inv * w.z; r.w = dw * inv * w.w;
    ((float4*)g_xn)[bt * 256 + tid] = r;
}

// ---------------- K_qkv: split-K GEMM partials. grid (16 otiles, 3 proj, 8 kchunks) ----------------
__global__ void __launch_bounds__(256) proj_kernel(const float* __restrict__ Wq,
                                                   const float* __restrict__ Wk,
                                                   const float* __restrict__ Wv) {
    const int o0 = blockIdx.x * 64;
    const int proj = blockIdx.y;
    const int chunk = blockIdx.z;
    const float* W = (proj == 0) ? Wq : ((proj == 1) ? Wk : Wv);
    __shared__ float As[64][SPP];
    __shared__ float Ws[64][SPP];
    const int tid = threadIdx.x;
    const int tx = tid & 15, ty = tid >> 4;
    float acc[4][4];
#pragma unroll
    for (int i = 0; i < 4; i++)
#pragma unroll
        for (int j = 0; j < 4; j++) acc[i][j] = 0.f;

#pragma unroll
    for (int kt = 0; kt < 2; kt++) {
        int k0 = chunk * 128 + kt * 64;
#pragma unroll
        for (int l = tid; l < 4096; l += 256) {
            int r = l >> 6, c = l & 63;
            As[r][c] = g_xn[r * 1024 + k0 + c];
            Ws[r][c] = __ldg(&W[(size_t)(o0 + r) * 1024 + k0 + c]);
        }
        __syncthreads();
#pragma unroll 8
        for (int kk = 0; kk < 64; kk++) {
            float a[4], w[4];
#pragma unroll
            for (int i = 0; i < 4; i++) a[i] = As[ty * 4 + i][kk];
#pragma unroll
            for (int j = 0; j < 4; j++) w[j] = Ws[tx * 4 + j][kk];
#pragma unroll
            for (int i = 0; i < 4; i++)
#pragma unroll
                for (int j = 0; j < 4; j++) acc[i][j] = fmaf(a[i], w[j], acc[i][j]);
        }
        __syncthreads();
    }

    float* dst = g_qkvp + (size_t)(proj * 8 + chunk) * 65536;
#pragma unroll
    for (int i = 0; i < 4; i++) {
        int tk = ty * 4 + i;
#pragma unroll
        for (int j = 0; j < 4; j++) {
            int o = o0 + tx * 4 + j;
            dst[tk * 1024 + o] = acc[i][j];
        }
    }
}

// ---------------- micro matmul: 2 outputs/thread, W transposed in smem ----------------
__device__ __forceinline__ void mmW(int d, int ts, const float* Wt, float bb,
                                    const float* in, float* outb) {
    const float4* lo = (const float4*)(in + ts * SP);
    const float4* hi = (const float4*)(in + (ts + 8) * SP);
    float a0 = 0.f, a1 = 0.f, a2 = 0.f, a3 = 0.f;
    float b0 = 0.f, b1 = 0.f, b2 = 0.f, b3 = 0.f;
#pragma unroll
    for (int jq = 0; jq < 16; jq++) {
        float4 x = lo[jq];
        float4 y = hi[jq];
        float w0 = Wt[(jq * 4 + 0) * SP + d];
        float w1 = Wt[(jq * 4 + 1) * SP + d];
        float w2 = Wt[(jq * 4 + 2) * SP + d];
        float w3 = Wt[(jq * 4 + 3) * SP + d];
        a0 = fmaf(x.x, w0, a0); a1 = fmaf(x.y, w1, a1);
        a2 = fmaf(x.z, w2, a2); a3 = fmaf(x.w, w3, a3);
        b0 = fmaf(y.x, w0, b0); b1 = fmaf(y.y, w1, b1);
        b2 = fmaf(y.z, w2, b2); b3 = fmaf(y.w, w3, b3);
    }
    outb[ts * SP + d] = ((a0 + a1) + (a2 + a3)) + bb;
    outb[(ts + 8) * SP + d] = ((b0 + b1) + (b2 + b3)) + bb;
}

__device__ __forceinline__ void loadWt(const float* __restrict__ W, float* Wt, int tid) {
    for (int idx = tid; idx < 4096; idx += 512) {
        int d = idx >> 6, j = idx & 63;
        Wt[j * SP + d] = __ldg(&W[idx]);
    }
}

// One inner iteration for one (b,h): 512 threads. ai returned in registers.
__device__ __forceinline__ void small_iter512(int tid,
        const float* Wtq, const float* Wtk, const float* Wtv,
        const float* __restrict__ blq, const float* __restrict__ blk,
        const float* __restrict__ blv,
        const float* __restrict__ lnc, const float* __restrict__ lnd,
        float tscale,
        const float* qin, const float* kin, const float* vin,
        float* tqb, float* klo, float* vlo, float* ksb, float* probs,
        float& ai_lo, float& ai_hi) {
    const int d = tid & 63, ts = tid >> 6;
    const int wid = tid >> 5, lane = tid & 31;

    mmW(d, ts, Wtq, __ldg(&blq[d]), qin, tqb);
    mmW(d, ts, Wtk, __ldg(&blk[d]), kin, klo);
    mmW(d, ts, Wtv, __ldg(&blv[d]), vin, vlo);
    __syncthreads();

    // LayerNorm(64): one warp per row; q rows in tqb (in place), k rows klo->ksb
    {
        int row = wid;
        float v0 = tqb[row * SP + lane], v1 = tqb[row * SP + lane + 32];
        float s = v0 + v1;
#pragma unroll
        for (int o = 16; o > 0; o >>= 1) s += __shfl_xor_sync(0xffffffffu, s, o);
        float m = s * (1.0f / 64.0f);
        float d0 = v0 - m, d1 = v1 - m;
        float q = fmaf(d0, d0, d1 * d1);
#pragma unroll
        for (int o = 16; o > 0; o >>= 1) q += __shfl_xor_sync(0xffffffffu, q, o);
        float inv = rsqrtf(q * (1.0f / 64.0f) + 1e-5f) * tscale;
        tqb[row * SP + lane] = d0 * inv * __ldg(&lnc[lane]);
        tqb[row * SP + lane + 32] = d1 * inv * __ldg(&lnc[lane + 32]);

        v0 = klo[row * SP + lane]; v1 = klo[row * SP + lane + 32];
        s = v0 + v1;
#pragma unroll
        for (int o = 16; o > 0; o >>= 1) s += __shfl_xor_sync(0xffffffffu, s, o);
        m = s * (1.0f / 64.0f);
        d0 = v0 - m; d1 = v1 - m;
        q = fmaf(d0, d0, d1 * d1);
#pragma unroll
        for (int o = 16; o > 0; o >>= 1) q += __shfl_xor_sync(0xffffffffu, q, o);
        inv = rsqrtf(q * (1.0f / 64.0f) + 1e-5f);
        ksb[row * SP + lane] = d0 * inv * __ldg(&lnd[lane]);
        ksb[row * SP + lane + 32] = d1 * inv * __ldg(&lnd[lane + 32]);
    }
    __syncthreads();

    // logits (16x16) * 1/8
    if (tid < 256) {
        int t = tid >> 4, s_ = tid & 15;
        const float4* a4 = (const float4*)(tqb + t * SP);
        const float4* k4 = (const float4*)(ksb + s_ * SP);
        float acc = 0.f;
#pragma unroll
        for (int jq = 0; jq < 16; jq++) {
            float4 a = a4[jq], k = k4[jq];
            acc = fmaf(a.x, k.x, acc); acc = fmaf(a.y, k.y, acc);
            acc = fmaf(a.z, k.z, acc); acc = fmaf(a.w, k.w, acc);
        }
        probs[tid] = acc * 0.125f;
    }
    __syncthreads();

    // softmax rows: one warp per row (lanes 16-31 mirror lanes 0-15)
    {
        int row = wid, s_ = lane & 15;
        float p = probs[row * 16 + s_];
        float mx = p;
#pragma unroll
        for (int o = 8; o > 0; o >>= 1) mx = fmaxf(mx, __shfl_xor_sync(0xffffffffu, mx, o));
        float ex = __expf(p - mx);
        float sm = ex;
#pragma unroll
        for (int o = 8; o > 0; o >>= 1) sm += __shfl_xor_sync(0xffffffffu, sm, o);
        probs[row * 16 + s_] = ex / sm;
    }
    __syncthreads();

    // ai = probs @ vl (2 outputs/thread, held in registers)
    {
        float a = 0.f, b = 0.f;
#pragma unroll
        for (int s_ = 0; s_ < 16; s_++) {
            float vv = vlo[s_ * SP + d];
            a = fmaf(probs[ts * 16 + s_], vv, a);
            b = fmaf(probs[(ts + 8) * 16 + s_], vv, b);
        }
        ai_lo = a; ai_hi = b;
    }
    __syncthreads();
}

// ---------------- K_iter01: iterations 0 and 1 + diff partials ----------------
__global__ void __launch_bounds__(512) iter01_kernel(
        const float* __restrict__ Wlq, const float* __restrict__ blq,
        const float* __restrict__ Wlk, const float* __restrict__ blk,
        const float* __restrict__ Wlv, const float* __restrict__ blv,
        const float* __restrict__ lnc, const float* __restrict__ lnd,
        const float* __restrict__ temp,
        const float* __restrict__ bq, const float* __restrict__ bv) {
    extern __shared__ float smx[];
    float* Wtq = smx + OFF_WTQ; float* Wtk = smx + OFF_WTK; float* Wtv = smx + OFF_WTV;
    float* qin = smx + OFF_QIN; float* kin = smx + OFF_KIN; float* vin = smx + OFF_VIN;
    float* tqb = smx + OFF_TQ;  float* klo = smx + OFF_KLO; float* vlo = smx + OFF_VLO;
    float* ksb = smx + OFF_KSB; float* probs = smx + OFF_PRB;
    const int bx = blockIdx.x, tid = threadIdx.x;
    const int b = bx >> 4, h = bx & 15;

    loadWt(Wlq, Wtq, tid);
    loadWt(Wlk, Wtk, tid);
    loadWt(Wlv, Wtv, tid);

    // reduce qkv split-K partials (fixed order), apply scale/bias
    const float SC = 0.35355339059327373f;   // 64^-0.25
    for (int e = tid; e < 1024; e += 512) {
        int t = e >> 6, dd = e & 63;
        int o = h * 64 + dd;
        int g = (b * 16 + t) * 1024 + o;
        float qv = 0.f, kv = 0.f, vv = 0.f;
#pragma unroll
        for (int c = 0; c < 8; c++) {
            qv += __ldg(&g_qkvp[(size_t)c * 65536 + g]);
            kv += __ldg(&g_qkvp[(size_t)(8 + c) * 65536 + g]);
            vv += __ldg(&g_qkvp[(size_t)(16 + c) * 65536 + g]);
        }
        qin[t * SP + dd] = (qv + __ldg(&bq[o])) * SC;
        kin[t * SP + dd] = kv * SC;
        vin[t * SP + dd] = vv + __ldg(&bv[o]);
    }
    __syncthreads();

    const float temp0 = __ldg(temp);
    float t0 = temp0;
    float ts0 = (t0 != 1.0f && t0 > 0.0f) ? rsqrtf(t0) : 1.0f;
    float ai0_lo, ai0_hi;
    small_iter512(tid, Wtq, Wtk, Wtv, blq, blk, blv, lnc, lnd, ts0,
                  qin, kin, vin, tqb, klo, vlo, ksb, probs, ai0_lo, ai0_hi);

    const int d = tid & 63, ts = tid >> 6;
    qin[ts * SP + d] += ai0_lo;
    qin[(ts + 8) * SP + d] += ai0_hi;
    __syncthreads();

    float t1 = temp0 + 0.005f;
    float ts1 = (t1 != 1.0f && t1 > 0.0f) ? rsqrtf(t1) : 1.0f;
    float ai1_lo, ai1_hi;
    // inputs: qin (updated), klo/vlo (kl0/vl0); outputs kl1->kin, vl1->vin
    small_iter512(tid, Wtq, Wtk, Wtv, blq, blk, blv, lnc, lnd, ts1,
                  qin, klo, vlo, tqb, kin, vin, ksb, probs, ai1_lo, ai1_hi);

    const int base = bx * 1024;
    const int elo = ts * 64 + d, ehi = (ts + 8) * 64 + d;
    g_ai1[base + elo] = ai1_lo;
    g_ai1[base + ehi] = ai1_hi;
    g_qc2[base + elo] = qin[ts * SP + d] + ai1_lo;
    g_qc2[base + ehi] = qin[(ts + 8) * SP + d] + ai1_hi;
    g_k2[base + elo] = kin[ts * SP + d];
    g_k2[base + ehi] = kin[(ts + 8) * SP + d];
    g_v2[base + elo] = vin[ts * SP + d];
    g_v2[base + ehi] = vin[(ts + 8) * SP + d];

    float psum = fabsf(ai1_lo - ai0_lo) + fabsf(ai1_hi - ai0_hi);
#pragma unroll
    for (int o = 16; o > 0; o >>= 1) psum += __shfl_xor_sync(0xffffffffu, psum, o);
    const int wid = tid >> 5, lane = tid & 31;
    if (lane == 0) probs[wid] = psum;
    __syncthreads();
    if (tid == 0) {
        float s = 0.f;
#pragma unroll
        for (int i = 0; i < 16; i++) s += probs[i];   // fixed order
        g_diffpart[bx] = s;
    }
}

// ---------------- K_iter2: diff check + conditional iteration 2 ----------------
__global__ void __launch_bounds__(512) iter2_kernel(
        const float* __restrict__ Wlq, const float* __restrict__ blq,
        const float* __restrict__ Wlk, const float* __restrict__ blk,
        const float* __restrict__ Wlv, const float* __restrict__ blv,
        const float* __restrict__ lnc, const float* __restrict__ lnd,
        const float* __restrict__ temp, const float* __restrict__ thrp,
        const float* __restrict__ facp) {
    extern __shared__ float smx[];
    float* Wtq = smx + OFF_WTQ; float* Wtk = smx + OFF_WTK; float* Wtv = smx + OFF_WTV;
    float* qin = smx + OFF_QIN; float* kin = smx + OFF_KIN; float* vin = smx + OFF_VIN;
    float* tqb = smx + OFF_TQ;  float* klo = smx + OFF_KLO; float* vlo = smx + OFF_VLO;
    float* ksb = smx + OFF_KSB; float* probs = smx + OFF_PRB;
    const int bx = blockIdx.x, tid = threadIdx.x;
    const int b = bx >> 4, h = bx & 15;

    if (tid < 64) probs[tid] = g_diffpart[tid];
    __syncthreads();
    if (tid == 0) {
        float s = 0.f;
#pragma unroll
        for (int i = 0; i < 64; i++) s += probs[i];   // fixed order: deterministic
        float diff = s * (1.0f / 8388608.0f);         // mean over B*H*T*hd
        float th = __ldg(thrp), fa = __ldg(facp);
        probs[64] = (diff < th + fa * diff) ? 1.0f : 0.0f;
    }
    __syncthreads();
    bool done = (probs[64] != 0.0f);

    if (done) {
        for (int e = tid; e < 1024; e += 512) {
            int t = e >> 6, dd = e & 63;
            g_aflat[(b * 16 + t) * 1024 + h * 64 + dd] = g_ai1[bx * 1024 + e];
        }
        return;
    }
    __syncthreads();

    loadWt(Wlq, Wtq, tid);
    loadWt(Wlk, Wtk, tid);
    loadWt(Wlv, Wtv, tid);
    for (int e = tid; e < 1024; e += 512) {
        int t = e >> 6, dd = e & 63, idx = t * SP + dd;
        qin[idx] = g_qc2[bx * 1024 + e];
        kin[idx] = g_k2[bx * 1024 + e];
        vin[idx] = g_v2[bx * 1024 + e];
    }
    __syncthreads();

    float t2 = __ldg(temp) + 0.01f;
    float ts2 = (t2 != 1.0f && t2 > 0.0f) ? rsqrtf(t2) : 1.0f;
    float ai_lo, ai_hi;
    small_iter512(tid, Wtq, Wtk, Wtv, blq, blk, blv, lnc, lnd, ts2,
                  qin, kin, vin, tqb, klo, vlo, ksb, probs, ai_lo, ai_hi);

    const int d = tid & 63, ts = tid >> 6;
    g_aflat[(b * 16 + ts) * 1024 + h * 64 + d] = ai_lo;
    g_aflat[(b * 16 + ts + 8) * 1024 + h * 64 + d] = ai_hi;
}

// ---------------- K_outproj: split-K partials. grid (16 otiles, 8 kchunks) ----------------
__global__ void __launch_bounds__(256) outproj_kernel(const float* __restrict__ Wo) {
    const int o0 = blockIdx.x * 64;
    const int chunk = blockIdx.y;
    __shared__ float As[64][SPP];
    __shared__ float Ws[64][SPP];
    const int tid = threadIdx.x;
    const int tx = tid & 15, ty = tid >> 4;
    float acc[4][4];
#pragma unroll
    for (int i = 0; i < 4; i++)
#pragma unroll
        for (int j = 0; j < 4; j++) acc[i][j] = 0.f;

#pragma unroll
    for (int kt = 0; kt < 2; kt++) {
        int k0 = chunk * 128 + kt * 64;
#pragma unroll
        for (int l = tid; l < 4096; l += 256) {
            int r = l >> 6, c = l & 63;
            As[r][c] = g_aflat[r * 1024 + k0 + c];
            Ws[r][c] = __ldg(&Wo[(size_t)(o0 + r) * 1024 + k0 + c]);
        }
        __syncthreads();
#pragma unroll 8
        for (int kk = 0; kk < 64; kk++) {
            float a[4], w[4];
#pragma unroll
            for (int i = 0; i < 4; i++) a[i] = As[ty * 4 + i][kk];
#pragma unroll
            for (int j = 0; j < 4; j++) w[j] = Ws[tx * 4 + j][kk];
#pragma unroll
            for (int i = 0; i < 4; i++)
#pragma unroll
                for (int j = 0; j < 4; j++) acc[i][j] = fmaf(a[i], w[j], acc[i][j]);
        }
        __syncthreads();
    }

    float* dst = g_outp + (size_t)chunk * 65536;
#pragma unroll
    for (int i = 0; i < 4; i++) {
        int tk = ty * 4 + i;
#pragma unroll
        for (int j = 0; j < 4; j++) {
            int o = o0 + tx * 4 + j;
            dst[tk * 1024 + o] = acc[i][j];
        }
    }
}

// ---------------- K_oreduce: fixed-order reduce of outproj partials + bo ----------------
__global__ void __launch_bounds__(256) oreduce_kernel(const float* __restrict__ bo,
                                                      float4* __restrict__ out) {
    const int tok = blockIdx.x;
    const int b = tok >> 4, t = tok & 15;
    const int tid = threadIdx.x;
    float4 s = __ldg(&((const float4*)bo)[tid]);
    const float4* p = (const float4*)g_outp;
#pragma unroll
    for (int c = 0; c < 8; c++) {
        float4 v = p[(size_t)(c * 64 + tok) * 256 + tid];
        s.x += v.x; s.y += v.y; s.z += v.z; s.w += v.w;
    }
    out[(size_t)(b * 2048 + t) * 256 + tid] = s;
}

extern "C" void kernel_launch(void* const* d_in, const int* in_sizes, int n_in,
                              void* d_out, int out_size) {
    const float* x    = (const float*)d_in[0];
    const float* Wq   = (const float*)d_in[1];
    const float* bq   = (const float*)d_in[2];
    const float* Wk   = (const float*)d_in[3];
    const float* Wv   = (const float*)d_in[4];
    const float* bv   = (const float*)d_in[5];
    const float* Wo   = (const float*)d_in[6];
    const float* bo   = (const float*)d_in[7];
    const float* lna  = (const float*)d_in[8];
    const float* lnc  = (const float*)d_in[9];
    const float* lnd  = (const float*)d_in[10];
    const float* Wlq  = (const float*)d_in[11];
    const float* blq  = (const float*)d_in[12];
    const float* Wlk  = (const float*)d_in[13];
    const float* blk  = (const float*)d_in[14];
    const float* Wlv  = (const float*)d_in[15];
    const float* blv  = (const float*)d_in[16];
    const float* temp = (const float*)d_in[17];
    const float* thr  = (const float*)d_in[18];
    const float* fac  = (const float*)d_in[19];
    float* out = (float*)d_out;

    cudaFuncSetAttribute(iter01_kernel, cudaFuncAttributeMaxDynamicSharedMemorySize, SMEM_ITER_BYTES);
    cudaFuncSetAttribute(iter2_kernel, cudaFuncAttributeMaxDynamicSharedMemorySize, SMEM_ITER_BYTES);

    fill_kernel<<<8192, 256>>>(bo, (float4*)out);
    ln_kernel<<<64, 256>>>(x, lna);
    proj_kernel<<<dim3(16, 3, 8), 256>>>(Wq, Wk, Wv);
    iter01_kernel<<<64, 512, SMEM_ITER_BYTES>>>(Wlq, blq, Wlk, blk, Wlv, blv, lnc, lnd, temp, bq, bv);
    iter2_kernel<<<64, 512, SMEM_ITER_BYTES>>>(Wlq, blq, Wlk, blk, Wlv, blv, lnc, lnd, temp, thr, fac);
    outproj_kernel<<<dim3(16, 8), 256>>>(Wo);
    oreduce_kernel<<<64, 256>>>(bo, (float4*)out);
}